// round 3
// baseline (speedup 1.0000x reference)
#include <cuda_runtime.h>

typedef unsigned long long ull;

#define S_LEN   2048
#define HDIM    16
#define TK      128
#define THREADS 128
#define NUM_H   8
#define NUM_B   4

// Float 0/1 mask (1 = keep, 0 = masked out), converted once per launch.
__device__ float gMaskF[NUM_B * S_LEN];

// Detect mask dtype on-device and convert to float keep-mask.
// Scans first 2048 int32 words (8192 bytes - valid under both layouts):
// int32 mask => all words in {0,1}; byte-bool mask => essentially never.
__global__ void mask_convert_kernel(const void* __restrict__ mask)
{
    __shared__ int s_all01;
    if (threadIdx.x == 0) s_all01 = 1;
    __syncthreads();

    const unsigned int* mi = (const unsigned int*)mask;
    int bad = 0;
    for (int i = threadIdx.x; i < 2048; i += blockDim.x)
        if (mi[i] > 1u) bad = 1;
    if (bad) s_all01 = 0;          // benign race: only writes 0
    __syncthreads();

    const int is_int32 = s_all01;
    const unsigned char* mb = (const unsigned char*)mask;
    for (int i = threadIdx.x; i < NUM_B * S_LEN; i += blockDim.x) {
        int masked = is_int32 ? (((const int*)mask)[i] != 0) : (mb[i] != 0);
        gMaskF[i] = masked ? 0.0f : 1.0f;
    }
}

// Packed fp32 math (sm_100+): fma.rn.f32x2 doubles FMA-pipe throughput
__device__ __forceinline__ float ex2f_(float x){ float r; asm("ex2.approx.f32 %0, %1;" : "=f"(r) : "f"(x)); return r; }
__device__ __forceinline__ float rcpf_(float x){ float r; asm("rcp.approx.f32 %0, %1;" : "=f"(r) : "f"(x)); return r; }
__device__ __forceinline__ ull ffma2(ull a, ull b, ull c){ ull d; asm("fma.rn.f32x2 %0, %1, %2, %3;" : "=l"(d) : "l"(a), "l"(b), "l"(c)); return d; }
__device__ __forceinline__ ull fadd2(ull a, ull b){ ull d; asm("add.rn.f32x2 %0, %1, %2;" : "=l"(d) : "l"(a), "l"(b)); return d; }
__device__ __forceinline__ ull pack2(float x){ ull d; asm("mov.b64 %0, {%1, %1};" : "=l"(d) : "f"(x)); return d; }
__device__ __forceinline__ float2 unpack2(ull v){ float2 r; asm("mov.b64 {%0, %1}, %2;" : "=f"(r.x), "=f"(r.y) : "l"(v)); return r; }

__global__ __launch_bounds__(THREADS) void attn_kernel(
    const float* __restrict__ Q, const float* __restrict__ K,
    const float* __restrict__ V, float* __restrict__ O)
{
    __shared__ __align__(16) float sK[TK * HDIM];
    __shared__ __align__(16) float sV[TK * HDIM];
    __shared__ __align__(16) float sM[TK];

    const int bh = blockIdx.y;
    const int b  = bh / NUM_H;
    const int q  = blockIdx.x * THREADS + threadIdx.x;
    const size_t base = (size_t)bh * S_LEN * HDIM;

    // p = exp(CLIP*tanh(SCALE*dot) - CLIP) = exp2(C2 / (exp2(C1*dot) + 1))
    // C1 = 2*SCALE*log2(e), C2 = -2*CLIP*log2(e)
    const float C1 = 1.1047776368247264f;
    const float C2 = -28.853900817779268f;

    ull qr[8];
    {
        const ulonglong2* qp = (const ulonglong2*)(Q + base + (size_t)q * HDIM);
        ulonglong2 a0 = qp[0], a1 = qp[1], a2 = qp[2], a3 = qp[3];
        qr[0]=a0.x; qr[1]=a0.y; qr[2]=a1.x; qr[3]=a1.y;
        qr[4]=a2.x; qr[5]=a2.y; qr[6]=a3.x; qr[7]=a3.y;
    }

    ull acc[8];
    #pragma unroll
    for (int i = 0; i < 8; i++) acc[i] = 0ull;
    float ssum = 0.f;

    for (int kt = 0; kt < S_LEN; kt += TK) {
        __syncthreads();
        // Stage K/V tile (TK x 16 fp32 each = 8KB each), fully coalesced
        const float4* Kg = (const float4*)(K + base + (size_t)kt * HDIM);
        const float4* Vg = (const float4*)(V + base + (size_t)kt * HDIM);
        float4* sK4 = (float4*)sK;
        float4* sV4 = (float4*)sV;
        #pragma unroll
        for (int i = 0; i < 4; i++) {
            sK4[threadIdx.x + i * THREADS] = Kg[threadIdx.x + i * THREADS];
            sV4[threadIdx.x + i * THREADS] = Vg[threadIdx.x + i * THREADS];
        }
        sM[threadIdx.x] = gMaskF[b * S_LEN + kt + threadIdx.x];
        __syncthreads();

        #pragma unroll 2
        for (int kk = 0; kk < TK; kk++) {
            const ull* kr = (const ull*)(sK + kk * HDIM);
            // QK dot: 8 packed FMAs as 2 chains (latency tree)
            ull d2a = 0ull, d2b = 0ull;
            #pragma unroll
            for (int i = 0; i < 4; i++) {
                d2a = ffma2(qr[2*i],     kr[2*i],     d2a);
                d2b = ffma2(qr[2*i + 1], kr[2*i + 1], d2b);
            }
            float2 dv = unpack2(fadd2(d2a, d2b));
            float dot = dv.x + dv.y;

            // clipped-tanh softmax weight with fixed max = +CLIP (legal: logits <= CLIP)
            float u = ex2f_(dot * C1);         // e^{2*SCALE*dot}
            float w = rcpf_(u + 1.0f);
            float p = ex2f_(C2 * w) * sM[kk];  // masked -> 0
            ssum += p;

            ull p2 = pack2(p);
            const ull* vr = (const ull*)(sV + kk * HDIM);
            #pragma unroll
            for (int i = 0; i < 8; i++) acc[i] = ffma2(p2, vr[i], acc[i]);
        }
    }

    float inv = 1.0f / ssum;
    float* op = O + base + (size_t)q * HDIM;
    #pragma unroll
    for (int i = 0; i < 4; i++) {
        float2 a  = unpack2(acc[2*i]);
        float2 bb = unpack2(acc[2*i + 1]);
        float4 o4;
        o4.x = a.x * inv; o4.y = a.y * inv;
        o4.z = bb.x * inv; o4.w = bb.y * inv;
        ((float4*)op)[i] = o4;
    }
}

extern "C" void kernel_launch(void* const* d_in, const int* in_sizes, int n_in,
                              void* d_out, int out_size) {
    const float* Q = (const float*)d_in[0];
    const float* K = (const float*)d_in[1];
    const float* V = (const float*)d_in[2];
    const void*  mask = d_in[3];
    float* O = (float*)d_out;

    mask_convert_kernel<<<1, 256>>>(mask);

    dim3 grid(S_LEN / THREADS, NUM_B * NUM_H);  // 16 q-tiles x (B*H)=32
    attn_kernel<<<grid, THREADS>>>(Q, K, V, O);
}

// round 5
// speedup vs baseline: 1.0408x; 1.0408x over previous
#include <cuda_runtime.h>

typedef unsigned long long ull;

#define S_LEN   2048
#define HDIM    16
#define TK      128
#define THREADS 128
#define NUM_H   8
#define NUM_B   4

// Additive mask bias: 0 = keep, -30000 = masked (ex2(-30000+x) flushes to 0).
__device__ float gMaskB[NUM_B * S_LEN];

// Detect mask dtype on-device (int32 vs byte bool) and convert to bias.
__global__ void mask_convert_kernel(const void* __restrict__ mask)
{
    __shared__ int s_all01;
    if (threadIdx.x == 0) s_all01 = 1;
    __syncthreads();

    const unsigned int* mi = (const unsigned int*)mask;
    int bad = 0;
    for (int i = threadIdx.x; i < 2048; i += blockDim.x)
        if (mi[i] > 1u) bad = 1;
    if (bad) s_all01 = 0;          // benign race: only writes 0
    __syncthreads();

    const int is_int32 = s_all01;
    const unsigned char* mb = (const unsigned char*)mask;
    for (int i = threadIdx.x; i < NUM_B * S_LEN; i += blockDim.x) {
        int masked = is_int32 ? (((const int*)mask)[i] != 0) : (mb[i] != 0);
        gMaskB[i] = masked ? -30000.0f : 0.0f;
    }
}

// Packed fp32 math (sm_100+)
__device__ __forceinline__ float ex2f_(float x){ float r; asm("ex2.approx.f32 %0, %1;" : "=f"(r) : "f"(x)); return r; }
__device__ __forceinline__ float rcpf_(float x){ float r; asm("rcp.approx.f32 %0, %1;" : "=f"(r) : "f"(x)); return r; }
__device__ __forceinline__ ull ffma2(ull a, ull b, ull c){ ull d; asm("fma.rn.f32x2 %0, %1, %2, %3;" : "=l"(d) : "l"(a), "l"(b), "l"(c)); return d; }
__device__ __forceinline__ ull fadd2(ull a, ull b){ ull d; asm("add.rn.f32x2 %0, %1, %2;" : "=l"(d) : "l"(a), "l"(b)); return d; }
__device__ __forceinline__ ull fmul2(ull a, ull b){ ull d; asm("mul.rn.f32x2 %0, %1, %2;" : "=l"(d) : "l"(a), "l"(b)); return d; }
__device__ __forceinline__ ull pack2(float x){ ull d; asm("mov.b64 %0, {%1, %1};" : "=l"(d) : "f"(x)); return d; }
__device__ __forceinline__ float2 unpack2(ull v){ float2 r; asm("mov.b64 {%0, %1}, %2;" : "=f"(r.x), "=f"(r.y) : "l"(v)); return r; }

__global__ __launch_bounds__(THREADS) void attn_kernel(
    const float* __restrict__ Q, const float* __restrict__ K,
    const float* __restrict__ V, float* __restrict__ O)
{
    __shared__ __align__(16) float sK[TK * HDIM];
    __shared__ __align__(16) float sV[TK * HDIM];
    __shared__ __align__(16) float sM[TK];

    const int bh = blockIdx.y;
    const int b  = bh / NUM_H;
    const int q  = blockIdx.x * THREADS + threadIdx.x;
    const size_t base = (size_t)bh * S_LEN * HDIM;

    // p = exp(CLIP*tanh(SCALE*dot) - CLIP) = exp2(C2 / (exp2(C1*dot) + 1))
    const float C1 = 1.1047776368247264f;   // 2*SCALE*log2(e)
    const float C2 = -28.853900817779268f;  // -2*CLIP*log2(e)

    // Load Q row, pre-scaled by C1 (so inner exp2 argument is just the dot)
    ull qs[8];
    {
        const ulonglong2* qp = (const ulonglong2*)(Q + base + (size_t)q * HDIM);
        ulonglong2 a0 = qp[0], a1 = qp[1], a2 = qp[2], a3 = qp[3];
        const ull c1p = pack2(C1);
        qs[0]=fmul2(a0.x,c1p); qs[1]=fmul2(a0.y,c1p);
        qs[2]=fmul2(a1.x,c1p); qs[3]=fmul2(a1.y,c1p);
        qs[4]=fmul2(a2.x,c1p); qs[5]=fmul2(a2.y,c1p);
        qs[6]=fmul2(a3.x,c1p); qs[7]=fmul2(a3.y,c1p);
    }

    ull acc[8];
    #pragma unroll
    for (int i = 0; i < 8; i++) acc[i] = 0ull;
    float ssum = 0.f;

    for (int kt = 0; kt < S_LEN; kt += TK) {
        __syncthreads();
        const float4* Kg = (const float4*)(K + base + (size_t)kt * HDIM);
        const float4* Vg = (const float4*)(V + base + (size_t)kt * HDIM);
        float4* sK4 = (float4*)sK;
        float4* sV4 = (float4*)sV;
        #pragma unroll
        for (int i = 0; i < 4; i++) {
            sK4[threadIdx.x + i * THREADS] = Kg[threadIdx.x + i * THREADS];
            sV4[threadIdx.x + i * THREADS] = Vg[threadIdx.x + i * THREADS];
        }
        sM[threadIdx.x] = gMaskB[b * S_LEN + kt + threadIdx.x];
        __syncthreads();

        #pragma unroll 2
        for (int kk = 0; kk < TK; kk += 4) {
            // One 128-bit mask load covers 4 keys
            float4 mk4 = *(const float4*)(sM + kk);
            #pragma unroll
            for (int j = 0; j < 4; j++) {
                const float mk = (j == 0) ? mk4.x : (j == 1) ? mk4.y : (j == 2) ? mk4.z : mk4.w;
                // K row: 4 x LDS.128
                const ulonglong2* kr = (const ulonglong2*)(sK + (kk + j) * HDIM);
                ulonglong2 k0 = kr[0], k1 = kr[1], k2 = kr[2], k3 = kr[3];

                ull d2a = ffma2(qs[0], k0.x, 0ull);
                ull d2b = ffma2(qs[1], k0.y, 0ull);
                d2a = ffma2(qs[2], k1.x, d2a);
                d2b = ffma2(qs[3], k1.y, d2b);
                d2a = ffma2(qs[4], k2.x, d2a);
                d2b = ffma2(qs[5], k2.y, d2b);
                d2a = ffma2(qs[6], k3.x, d2a);
                d2b = ffma2(qs[7], k3.y, d2b);
                float2 dv = unpack2(fadd2(d2a, d2b));
                float dot = dv.x + dv.y;                // = C1 * (q . k)

                float u = ex2f_(dot);                   // e^{2*SCALE*(q.k)}
                float w = rcpf_(u + 1.0f);
                float p = ex2f_(fmaf(C2, w, mk));       // masked -> exact 0
                ssum += p;

                // V row: 4 x LDS.128
                const ulonglong2* vr = (const ulonglong2*)(sV + (kk + j) * HDIM);
                ulonglong2 v0 = vr[0], v1 = vr[1], v2 = vr[2], v3 = vr[3];
                ull p2 = pack2(p);
                acc[0] = ffma2(p2, v0.x, acc[0]);
                acc[1] = ffma2(p2, v0.y, acc[1]);
                acc[2] = ffma2(p2, v1.x, acc[2]);
                acc[3] = ffma2(p2, v1.y, acc[3]);
                acc[4] = ffma2(p2, v2.x, acc[4]);
                acc[5] = ffma2(p2, v2.y, acc[5]);
                acc[6] = ffma2(p2, v3.x, acc[6]);
                acc[7] = ffma2(p2, v3.y, acc[7]);
            }
        }
    }

    float inv = 1.0f / ssum;
    float* op = O + base + (size_t)q * HDIM;
    #pragma unroll
    for (int i = 0; i < 4; i++) {
        float2 a  = unpack2(acc[2*i]);
        float2 bb = unpack2(acc[2*i + 1]);
        float4 o4;
        o4.x = a.x * inv; o4.y = a.y * inv;
        o4.z = bb.x * inv; o4.w = bb.y * inv;
        ((float4*)op)[i] = o4;
    }
}

extern "C" void kernel_launch(void* const* d_in, const int* in_sizes, int n_in,
                              void* d_out, int out_size) {
    const float* Q = (const float*)d_in[0];
    const float* K = (const float*)d_in[1];
    const float* V = (const float*)d_in[2];
    const void*  mask = d_in[3];
    float* O = (float*)d_out;

    mask_convert_kernel<<<1, 256>>>(mask);

    dim3 grid(S_LEN / THREADS, NUM_B * NUM_H);
    attn_kernel<<<grid, THREADS>>>(Q, K, V, O);
}